// round 8
// baseline (speedup 1.0000x reference)
#include <cuda_runtime.h>
#include <math.h>

#define HH 1024
#define WW 1024
#define PLANES 24           // 8 batch * 3 channels
#define RAD 25
#define TAPS 51

// 100 MB scratch for the horizontal-pass result (no cudaMalloc allowed)
__device__ float g_tmp[(size_t)PLANES * HH * WW];

// ---------------- compile-time gaussian weights -> FFMA immediates ----------
struct WTab { float w[TAPS]; };

__host__ __device__ constexpr double cexp_series(double x) {
    double term = 1.0, sum = 1.0;
    for (int i = 1; i < 40; ++i) { term *= x / (double)i; sum += term; }
    return sum;
}

__host__ __device__ constexpr WTab make_wtab() {
    WTab t{};
    double g[TAPS] = {};
    double s = 0.0;
    for (int i = 0; i < TAPS; ++i) {
        double d = (double)(i - RAD);
        g[i] = cexp_series(-d * d / (2.0 * 15.0 * 15.0));
        s += g[i];
    }
    for (int i = 0; i < TAPS; ++i) t.w[i] = (float)(g[i] / s);
    return t;
}

// ---------------- pass 1: horizontal 51-tap conv ----------------------------
// One block = one image row. 128 threads, 8 outputs/thread.
// Skew i + (i>>3): lane word = 8l + k -> skewed addr = 9l + k + k/8,
// and 9l mod 32 is a bijection over 32 lanes -> conflict-free for EVERY k.
#define SKW(i) ((i) + ((i) >> 3))

__global__ void __launch_bounds__(128) hpass(const float* __restrict__ x) {
    const int row = blockIdx.x;                       // 0 .. PLANES*HH-1
    const float* src = x + (size_t)row * WW;
    float* dst = g_tmp + (size_t)row * WW;

    __shared__ float s[SKW(WW + 2 * RAD - 1) + 2];    // ~1209 floats, 4.8 KB

    const int tid = threadIdx.x;
    for (int i = tid; i < WW + 2 * RAD; i += 128) {
        int j = i - RAD;
        s[SKW(i)] = (j >= 0 && j < WW) ? src[j] : 0.0f;
    }
    __syncthreads();

    constexpr WTab WT = make_wtab();
    const int b = tid * 8;

    float acc[8] = {0.f, 0.f, 0.f, 0.f, 0.f, 0.f, 0.f, 0.f};
    #pragma unroll
    for (int k = 0; k <= 57; ++k) {                   // window of 58 values
        const float v = s[SKW(b + k)];
        #pragma unroll
        for (int i = 0; i < 8; ++i) {
            if (k - i >= 0 && k - i <= 2 * RAD)
                acc[i] += WT.w[k - i] * v;            // compile-time w -> FFMA-imm
        }
    }

    reinterpret_cast<float4*>(dst + b)[0] = make_float4(acc[0], acc[1], acc[2], acc[3]);
    reinterpret_cast<float4*>(dst + b)[1] = make_float4(acc[4], acc[5], acc[6], acc[7]);
}

// ---------------- pass 2: vertical 51-tap conv + screen blend ---------------
// Block: 256 threads. Tile: 128 cols x 32 output rows; smem 82 x 128 = 42 KB.
// Thread (c = tid&127, h = tid>>7) computes rows h*16 .. h*16+15 of column c.
// smem reads s[k][c]: lane -> bank identity, conflict-free broadcast-free.
#define TYV 32
#define SRV (TYV + 2 * RAD)     // 82

__global__ void __launch_bounds__(256) vpass(const float* __restrict__ x,
                                             const float* __restrict__ amt_p,
                                             float* __restrict__ out) {
    __shared__ float s[SRV][128];

    const int tid = threadIdx.x;
    const int plane = blockIdx.z;
    const int x0 = blockIdx.x * 128;
    const int y0 = blockIdx.y * TYV;
    const float* tp = g_tmp + (size_t)plane * HH * WW;

    // Cooperative float4 fill of the 82x128 tile (2624 float4s / 256 threads)
    for (int i = tid; i < SRV * 32; i += 256) {
        int r = i >> 5, c4 = (i & 31) << 2;
        int gy = y0 - RAD + r;
        float4 v = make_float4(0.f, 0.f, 0.f, 0.f);
        if ((unsigned)gy < HH)
            v = *reinterpret_cast<const float4*>(tp + (size_t)gy * WW + x0 + c4);
        *reinterpret_cast<float4*>(&s[r][c4]) = v;
    }
    __syncthreads();

    constexpr WTab WT = make_wtab();
    const int c = tid & 127;
    const int rbase = (tid >> 7) * 16;   // 0 or 16

    float acc[16];
    #pragma unroll
    for (int i = 0; i < 16; ++i) acc[i] = 0.0f;

    // output local row rbase+ii needs smem rows (rbase+ii) .. (rbase+ii+50)
    #pragma unroll
    for (int k = 0; k <= 15 + 2 * RAD; ++k) {        // 66 smem reads
        const float v = s[rbase + k][c];
        #pragma unroll
        for (int ii = 0; ii < 16; ++ii) {
            if (k - ii >= 0 && k - ii <= 2 * RAD)
                acc[ii] += WT.w[k - ii] * v;          // FFMA-imm
        }
    }

    // amount = sigmoid(param) * 0.4 ; result = clip(x + blur*1.2*amount*(1-x))
    const float amount = 0.4f / (1.0f + expf(-amt_p[0]));
    const float kk = 1.2f * amount;

    const float* xp = x + (size_t)plane * HH * WW;
    float* op = out + (size_t)plane * HH * WW;

    #pragma unroll
    for (int ii = 0; ii < 16; ++ii) {
        const size_t off = (size_t)(y0 + rbase + ii) * WW + x0 + c;
        const float xv = xp[off];
        float r = fmaf(acc[ii] * kk, 1.0f - xv, xv);
        r = fminf(fmaxf(r, 0.0f), 1.0f);
        op[off] = r;
    }
}

extern "C" void kernel_launch(void* const* d_in, const int* in_sizes, int n_in,
                              void* d_out, int out_size) {
    const float* x   = (const float*)d_in[0];
    const float* amt = (const float*)d_in[1];
    float* out = (float*)d_out;

    hpass<<<PLANES * HH, 128>>>(x);
    dim3 grid(WW / 128, HH / TYV, PLANES);
    vpass<<<grid, 256>>>(x, amt, out);
}

// round 9
// speedup vs baseline: 1.8949x; 1.8949x over previous
#include <cuda_runtime.h>
#include <math.h>

#define HH 1024
#define WW 1024
#define PLANES 24           // 8 batch * 3 channels
#define RAD 25
#define TAPS 51

// 100 MB scratch for the horizontal-pass result (no cudaMalloc allowed)
__device__ float g_tmp[(size_t)PLANES * HH * WW];

// ---------------- compile-time gaussian weights -> FFMA immediates ----------
struct WTab { float w[TAPS]; };

__host__ __device__ constexpr double cexp_series(double x) {
    double term = 1.0, sum = 1.0;
    for (int i = 1; i < 40; ++i) { term *= x / (double)i; sum += term; }
    return sum;
}

__host__ __device__ constexpr WTab make_wtab() {
    WTab t{};
    double g[TAPS] = {};
    double s = 0.0;
    for (int i = 0; i < TAPS; ++i) {
        double d = (double)(i - RAD);
        g[i] = cexp_series(-d * d / (2.0 * 15.0 * 15.0));
        s += g[i];
    }
    for (int i = 0; i < TAPS; ++i) t.w[i] = (float)(g[i] / s);
    return t;
}

__constant__ WTab c_wt = make_wtab();

// ---------------- packed f32x2 helpers (vpass only) -----------------------
__device__ __forceinline__ unsigned long long pk2(float a, float b) {
    unsigned long long r;
    asm("mov.b64 %0, {%1, %2};" : "=l"(r) : "f"(a), "f"(b));
    return r;
}
__device__ __forceinline__ void upk2(unsigned long long v, float& a, float& b) {
    asm("mov.b64 {%0, %1}, %2;" : "=f"(a), "=f"(b) : "l"(v));
}
__device__ __forceinline__ unsigned long long ffma2(unsigned long long a,
                                                    unsigned long long b,
                                                    unsigned long long c) {
    unsigned long long d;
    asm("fma.rn.f32x2 %0, %1, %2, %3;" : "=l"(d) : "l"(a), "l"(b), "l"(c));
    return d;
}

// ---------------- pass 1: horizontal 51-tap conv ----------------------------
// One block = one image row, 256 threads, 4 outputs/thread.
// Window loads: float4 index tid + k4 -> consecutive lanes hit consecutive
// 16B units -> LDS.128 fully conflict-free. Weights are compile-time consts.
__global__ void __launch_bounds__(256) hpass(const float* __restrict__ x) {
    const int row = blockIdx.x;                       // 0 .. PLANES*HH-1
    const float* src = x + (size_t)row * WW;
    float* dst = g_tmp + (size_t)row * WW;

    __shared__ __align__(16) float s[WW + 2 * RAD + 6];   // 1080 floats

    const int tid = threadIdx.x;
    #pragma unroll
    for (int t = 0; t < 5; ++t) {                    // 5*256 >= 1080
        int i = tid + t * 256;
        if (i < WW + 2 * RAD + 6) {
            int j = i - RAD;
            s[i] = (j >= 0 && j < WW) ? src[j] : 0.0f;
        }
    }
    __syncthreads();

    constexpr WTab WT = make_wtab();
    const int b = tid * 4;                           // outputs b..b+3
    const float4* s4 = reinterpret_cast<const float4*>(s);

    float acc[4] = {0.f, 0.f, 0.f, 0.f};
    #pragma unroll
    for (int k4 = 0; k4 < 14; ++k4) {                // window floats 0..55
        float4 v4 = s4[tid + k4];
        float vv[4] = {v4.x, v4.y, v4.z, v4.w};
        #pragma unroll
        for (int q = 0; q < 4; ++q) {
            const int k = 4 * k4 + q;
            #pragma unroll
            for (int i = 0; i < 4; ++i) {
                if (k - i >= 0 && k - i <= 2 * RAD)
                    acc[i] += WT.w[k - i] * vv[q];   // compile-time w -> FFMA-imm
            }
        }
    }

    *reinterpret_cast<float4*>(dst + b) = make_float4(acc[0], acc[1], acc[2], acc[3]);
}

// ---------------- pass 2: vertical 51-tap conv + blend (packed) ----------
// Block: 256 threads. Tile: 128 cols x 32 rows; smem 82 x 128 = 42 KB.
// Thread: col pair p = tid&63 (cols 2p,2p+1), quarter h = tid>>6 -> 8 rows.
// LDS.64 at &s[row][2p]: consecutive lanes -> consecutive 8B, conflict-free.
#define TYV 32
#define SRV (TYV + 2 * RAD)     // 82

__global__ void __launch_bounds__(256) vpass(const float* __restrict__ x,
                                             const float* __restrict__ amt_p,
                                             float* __restrict__ out) {
    __shared__ float s[SRV][128];
    __shared__ unsigned long long wb[TAPS];

    const int tid = threadIdx.x;
    if (tid < TAPS) wb[tid] = pk2(c_wt.w[tid], c_wt.w[tid]);

    const int plane = blockIdx.z;
    const int x0 = blockIdx.x * 128;
    const int y0 = blockIdx.y * TYV;
    const float* tp = g_tmp + (size_t)plane * HH * WW;

    // Cooperative float4 fill of the 82x128 tile
    #pragma unroll
    for (int t = 0; t < 11; ++t) {                   // 11*256 >= 82*32
        int i = tid + t * 256;
        if (i < SRV * 32) {
            int r = i >> 5, c4 = (i & 31) << 2;
            int gy = y0 - RAD + r;
            float4 v = make_float4(0.f, 0.f, 0.f, 0.f);
            if ((unsigned)gy < HH)
                v = *reinterpret_cast<const float4*>(tp + (size_t)gy * WW + x0 + c4);
            *reinterpret_cast<float4*>(&s[r][c4]) = v;
        }
    }
    __syncthreads();

    const int p = tid & 63;          // column pair (cols 2p, 2p+1)
    const int h = tid >> 6;          // row quarter: 8 rows
    const int rbase = h * 8;

    unsigned long long v[8];
    #pragma unroll
    for (int j = 0; j < 7; ++j)
        v[j] = *reinterpret_cast<const unsigned long long*>(&s[rbase + j][2 * p]);

    unsigned long long acc[8];
    #pragma unroll
    for (int i = 0; i < 8; ++i) acc[i] = 0ull;

    #pragma unroll
    for (int d = 0; d <= 50; ++d) {
        v[(d + 7) & 7] =
            *reinterpret_cast<const unsigned long long*>(&s[rbase + d + 7][2 * p]);
        unsigned long long wd = wb[d];
        #pragma unroll
        for (int ii = 0; ii < 8; ++ii)
            acc[ii] = ffma2(v[(d + ii) & 7], wd, acc[ii]);
    }

    // amount = sigmoid(param) * 0.4 ; result = clip(x + blur*1.2*amount*(1-x))
    const float amount = 0.4f / (1.0f + expf(-amt_p[0]));
    const float kk = 1.2f * amount;

    const float* xp = x + (size_t)plane * HH * WW;
    float* op = out + (size_t)plane * HH * WW;

    #pragma unroll
    for (int ii = 0; ii < 8; ++ii) {
        const int gy = y0 + rbase + ii;
        const size_t off = (size_t)gy * WW + x0 + 2 * p;
        float2 xv = *reinterpret_cast<const float2*>(xp + off);
        float b0, b1;
        upk2(acc[ii], b0, b1);
        float r0 = xv.x + b0 * kk * (1.0f - xv.x);
        float r1 = xv.y + b1 * kk * (1.0f - xv.y);
        r0 = fminf(fmaxf(r0, 0.0f), 1.0f);
        r1 = fminf(fmaxf(r1, 0.0f), 1.0f);
        *reinterpret_cast<float2*>(op + off) = make_float2(r0, r1);
    }
}

extern "C" void kernel_launch(void* const* d_in, const int* in_sizes, int n_in,
                              void* d_out, int out_size) {
    const float* x   = (const float*)d_in[0];
    const float* amt = (const float*)d_in[1];
    float* out = (float*)d_out;

    hpass<<<PLANES * HH, 256>>>(x);
    dim3 grid(WW / 128, HH / TYV, PLANES);
    vpass<<<grid, 256>>>(x, amt, out);
}